// round 4
// baseline (speedup 1.0000x reference)
#include <cuda_runtime.h>

#define BB 64
#define TT 512
#define II 512
#define HH 1024

#define NBLK 128
#define NTHR 128
#define KC 64

// [g][t][b][h] input-side gate pre-activations (402 MB)
__device__ float g_xg[(size_t)3 * TT * BB * HH];
// double-buffered hidden state
__device__ float g_h[2][BB * HH];
// grid barrier state
__device__ unsigned g_bar;
__device__ unsigned g_gen;

__device__ __forceinline__ void gridbar(unsigned& gen) {
    __syncthreads();
    gen++;
    if (threadIdx.x == 0) {
        __threadfence();
        unsigned arr = atomicAdd(&g_bar, 1u);
        if (arr == NBLK - 1) {
            g_bar = 0;
            __threadfence();
            atomicExch(&g_gen, gen);
        } else {
            volatile unsigned* vg = &g_gen;
            while (*vg < gen) { }
            __threadfence();
        }
    }
    __syncthreads();
}

// ---------------------------------------------------------------------------
// Phase 1: Xg[t][b][h] = x[b][t][:] . Wg[h][:] + bias_g[h]   (3 gates)
// Block tile 128m x 64n, 256 threads, thread tile 8m x 4n, Kc = 16.
// ---------------------------------------------------------------------------
__global__ __launch_bounds__(256, 2) void gemm_in(
    const float* __restrict__ x,
    const float* __restrict__ W0, const float* __restrict__ W1, const float* __restrict__ W2,
    const float* __restrict__ c0, const float* __restrict__ c1, const float* __restrict__ c2)
{
    __shared__ float As[16][128];
    __shared__ float Bs[16][64];
    const int g = blockIdx.z;
    const float* W    = (g == 0) ? W0 : (g == 1) ? W1 : W2;
    const float* bias = (g == 0) ? c0 : (g == 1) ? c1 : c2;
    const int m0 = blockIdx.y * 128;
    const int n0 = blockIdx.x * 64;
    const int tid = threadIdx.x;
    const int n_thr = tid & 15;   // n varies fastest within warp -> coalesced C stores
    const int m_thr = tid >> 4;
    const int ar = tid >> 1, ak = (tid & 1) * 8;
    const int brow = tid >> 2, bk = (tid & 3) * 4;

    float acc[8][4];
#pragma unroll
    for (int i = 0; i < 8; i++)
#pragma unroll
        for (int j = 0; j < 4; j++) acc[i][j] = 0.f;

    for (int k0 = 0; k0 < II; k0 += 16) {
        float4 a0 = *(const float4*)&x[(size_t)(m0 + ar) * II + k0 + ak];
        float4 a1 = *(const float4*)&x[(size_t)(m0 + ar) * II + k0 + ak + 4];
        float4 bv = *(const float4*)&W[(size_t)(n0 + brow) * II + k0 + bk];
        As[ak + 0][ar] = a0.x; As[ak + 1][ar] = a0.y; As[ak + 2][ar] = a0.z; As[ak + 3][ar] = a0.w;
        As[ak + 4][ar] = a1.x; As[ak + 5][ar] = a1.y; As[ak + 6][ar] = a1.z; As[ak + 7][ar] = a1.w;
        Bs[bk + 0][brow] = bv.x; Bs[bk + 1][brow] = bv.y; Bs[bk + 2][brow] = bv.z; Bs[bk + 3][brow] = bv.w;
        __syncthreads();
#pragma unroll
        for (int k = 0; k < 16; k++) {
            float a[8], bb[4];
            *(float4*)&a[0] = *(const float4*)&As[k][m_thr * 8];
            *(float4*)&a[4] = *(const float4*)&As[k][m_thr * 8 + 4];
            *(float4*)&bb[0] = *(const float4*)&Bs[k][n_thr * 4];
#pragma unroll
            for (int i = 0; i < 8; i++)
#pragma unroll
                for (int j = 0; j < 4; j++) acc[i][j] += a[i] * bb[j];
        }
        __syncthreads();
    }

    float4 bs4 = *(const float4*)&bias[n0 + n_thr * 4];
#pragma unroll
    for (int i = 0; i < 8; i++) {
        int m = m0 + m_thr * 8 + i;
        int b = m >> 9;      // m = b*T + t, T = 512
        int t = m & 511;
        float4 o;
        o.x = acc[i][0] + bs4.x; o.y = acc[i][1] + bs4.y;
        o.z = acc[i][2] + bs4.z; o.w = acc[i][3] + bs4.w;
        *(float4*)&g_xg[(((size_t)g * TT + t) * BB + b) * HH + n0 + n_thr * 4] = o;
    }
}

// ---------------------------------------------------------------------------
// Phase 2: persistent kernel, 512 sequential GRU steps.
// 128 blocks x 128 threads. Block owns all 64 batches x 8 h-columns x 3 gates.
// W_h slices (96 KB) live in SMEM for the whole kernel. h double-buffered in
// global; staged per 64-k chunk into SMEM (transposed [k][b]) with reg prefetch.
// Thread tile: 4b x 1h x 3g.  One software grid barrier per step.
// ---------------------------------------------------------------------------
__global__ __launch_bounds__(NTHR, 1) void gru_steps(
    const float* __restrict__ Whr, const float* __restrict__ Whi, const float* __restrict__ Whn,
    float* __restrict__ out, int write_hlast)
{
    extern __shared__ float smem[];
    float* Ws = smem;                   // [3][8][HH]  = 24576 floats
    float* hs = smem + 3 * 8 * HH;      // [2][KC][64] =  8192 floats

    const int tid = threadIdx.x;
    const int ht = blockIdx.x;
    const int h0 = ht * 8;
    const int h_thr = tid & 7;
    const int b_thr = tid >> 3;         // [0,16)
    const int b4 = b_thr * 4;
    const int h = h0 + h_thr;
    const int b_ld = tid >> 1;          // [0,64)  staging row
    const int kofs = (tid & 1) * 32;    // staging k-half

    // Load this block's W_h slices into SMEM once (persist across all steps).
    for (int pass = 0; pass < 3; pass++) {
        const float* W = (pass == 0) ? Whr : (pass == 1) ? Whi : Whn;
        for (int idx = tid; idx < 8 * (HH / 4); idx += NTHR) {
            int r = idx >> 8;           // HH/4 = 256
            int kk = idx & 255;
            float4 v = *(const float4*)&W[(size_t)(h0 + r) * HH + kk * 4];
            *(float4*)&Ws[((size_t)pass * 8 + r) * HH + kk * 4] = v;
        }
    }

    // Zero h[0] (this block's 512-float slice of the 64x1024 state).
    {
        float* hz = &g_h[0][0];
        for (int i = tid; i < 512; i += NTHR) hz[ht * 512 + i] = 0.f;
    }

    unsigned gen = *(volatile unsigned*)&g_gen;   // snapshot (safe: no barrier can
                                                  // complete before all blocks snapshot)
    gridbar(gen);

    const float* wr_row = &Ws[(0 * 8 + h_thr) * HH];
    const float* wi_row = &Ws[(1 * 8 + h_thr) * HH];
    const float* wn_row = &Ws[(2 * 8 + h_thr) * HH];

    for (int t = 0; t < TT; t++) {
        const float* hcur = g_h[t & 1];
        float* hnxt = g_h[(t & 1) ^ 1];

        float ar[4] = {0.f, 0.f, 0.f, 0.f};
        float ai[4] = {0.f, 0.f, 0.f, 0.f};
        float an[4] = {0.f, 0.f, 0.f, 0.f};

        // Prologue: stage chunk 0 into hs buffer 0 (transposed [k][b]).
        {
            const float* src = hcur + (size_t)b_ld * HH + kofs;
            float* d = hs;
#pragma unroll
            for (int j = 0; j < 8; j++) {
                float4 p = __ldcg((const float4*)(src + j * 4));
                d[(kofs + j * 4 + 0) * 64 + b_ld] = p.x;
                d[(kofs + j * 4 + 1) * 64 + b_ld] = p.y;
                d[(kofs + j * 4 + 2) * 64 + b_ld] = p.z;
                d[(kofs + j * 4 + 3) * 64 + b_ld] = p.w;
            }
        }
        __syncthreads();

        int buf = 0;
        for (int kc = 0; kc < HH; kc += KC) {
            float4 pf[8];
            const bool nxt = (kc + KC) < HH;
            if (nxt) {
                const float* src = hcur + (size_t)b_ld * HH + kc + KC + kofs;
#pragma unroll
                for (int j = 0; j < 8; j++) pf[j] = __ldcg((const float4*)(src + j * 4));
            }
            const float* hsb = hs + buf * (KC * 64);
#pragma unroll
            for (int k4 = 0; k4 < KC; k4 += 4) {
                float4 wr = *(const float4*)(wr_row + kc + k4);
                float4 wi = *(const float4*)(wi_row + kc + k4);
                float4 wn = *(const float4*)(wn_row + kc + k4);
#pragma unroll
                for (int q = 0; q < 4; q++) {
                    float4 hv = *(const float4*)(hsb + (k4 + q) * 64 + b4);
                    float fr = (q == 0) ? wr.x : (q == 1) ? wr.y : (q == 2) ? wr.z : wr.w;
                    float fi = (q == 0) ? wi.x : (q == 1) ? wi.y : (q == 2) ? wi.z : wi.w;
                    float fn = (q == 0) ? wn.x : (q == 1) ? wn.y : (q == 2) ? wn.z : wn.w;
                    ar[0] += hv.x * fr; ar[1] += hv.y * fr; ar[2] += hv.z * fr; ar[3] += hv.w * fr;
                    ai[0] += hv.x * fi; ai[1] += hv.y * fi; ai[2] += hv.z * fi; ai[3] += hv.w * fi;
                    an[0] += hv.x * fn; an[1] += hv.y * fn; an[2] += hv.z * fn; an[3] += hv.w * fn;
                }
            }
            if (nxt) {
                __syncthreads();
                float* d = hs + (buf ^ 1) * (KC * 64);
#pragma unroll
                for (int j = 0; j < 8; j++) {
                    d[(kofs + j * 4 + 0) * 64 + b_ld] = pf[j].x;
                    d[(kofs + j * 4 + 1) * 64 + b_ld] = pf[j].y;
                    d[(kofs + j * 4 + 2) * 64 + b_ld] = pf[j].z;
                    d[(kofs + j * 4 + 3) * 64 + b_ld] = pf[j].w;
                }
                __syncthreads();
                buf ^= 1;
            }
        }

        // Gate update for this thread's 4 batches at column h.
        const size_t xoff = (size_t)t * BB * HH;
        const float* xr_p = g_xg + xoff;
        const float* xi_p = g_xg + (size_t)TT * BB * HH + xoff;
        const float* xn_p = g_xg + 2 * (size_t)TT * BB * HH + xoff;
#pragma unroll
        for (int c = 0; c < 4; c++) {
            const int b = b4 + c;
            const size_t ix = (size_t)b * HH + h;
            float xr = xr_p[ix];
            float xi = xi_p[ix];
            float xn = xn_p[ix];
            float hp = __ldcg(&hcur[ix]);
            float rg = __fdividef(1.f, 1.f + __expf(-(xr + ar[c])));
            float ig = __fdividef(1.f, 1.f + __expf(-(xi + ai[c])));
            float zi = xn + rg * an[c];
            float ng = 1.f - __fdividef(2.f, __expf(2.f * zi) + 1.f);   // tanh(zi)
            float hn = (1.f - ig) * ng + ig * hp;
            hnxt[ix] = hn;
            out[((size_t)b * TT + t) * HH + h] = hn;
            if (write_hlast && t == TT - 1)
                out[(size_t)BB * TT * HH + ix] = hn;
        }

        if (t < TT - 1) gridbar(gen);
    }
}

extern "C" void kernel_launch(void* const* d_in, const int* in_sizes, int n_in,
                              void* d_out, int out_size) {
    const float* x   = (const float*)d_in[0];
    const float* Wir = (const float*)d_in[1];
    const float* Wii = (const float*)d_in[2];
    const float* Win = (const float*)d_in[3];
    const float* bir = (const float*)d_in[4];
    const float* bii = (const float*)d_in[5];
    const float* bin = (const float*)d_in[6];
    const float* Whr = (const float*)d_in[7];
    const float* Whi = (const float*)d_in[8];
    const float* Whn = (const float*)d_in[9];
    float* out = (float*)d_out;

    // Phase 1: input-side projections for all 3 gates.
    dim3 g1(HH / 64, (BB * TT) / 128, 3);
    gemm_in<<<g1, 256>>>(x, Wir, Wii, Win, bir, bii, bin);

    // Phase 2: persistent recurrence kernel.
    const int smem_bytes = (3 * 8 * HH + 2 * KC * 64) * (int)sizeof(float);  // 131072
    cudaFuncSetAttribute(gru_steps, cudaFuncAttributeMaxDynamicSharedMemorySize, smem_bytes);
    int write_hlast = (out_size >= BB * TT * HH + BB * HH) ? 1 : 0;
    gru_steps<<<NBLK, NTHR, smem_bytes>>>(Whr, Whi, Whn, out, write_hlast);
}

// round 9
// speedup vs baseline: 3.4733x; 3.4733x over previous
#include <cuda_runtime.h>

#define BB 64
#define TT 512
#define II 512
#define HH 1024

#define NBLK 128
#define NTHR 256

// [g][t][b][h] input-side gate pre-activations (402 MB)
__device__ float g_xg[(size_t)3 * TT * BB * HH];
// double-buffered hidden state
__device__ float g_h[2][BB * HH];
// grid barrier state
__device__ unsigned g_bar;
__device__ unsigned g_gen;

__device__ __forceinline__ void gridbar(unsigned& gen) {
    __syncthreads();
    gen++;
    if (threadIdx.x == 0) {
        __threadfence();
        unsigned arr = atomicAdd(&g_bar, 1u);
        if (arr == NBLK - 1) {
            g_bar = 0;
            __threadfence();
            atomicExch(&g_gen, gen);
        } else {
            volatile unsigned* vg = &g_gen;
            while (*vg < gen) { }
            __threadfence();
        }
    }
    __syncthreads();
}

__device__ __forceinline__ void cp_async16(void* smem_dst, const void* gsrc) {
    unsigned s = (unsigned)__cvta_generic_to_shared(smem_dst);
    asm volatile("cp.async.cg.shared.global [%0], [%1], 16;\n" :: "r"(s), "l"(gsrc));
}
#define CP_COMMIT() asm volatile("cp.async.commit_group;\n" ::: "memory")
#define CP_WAIT(n)  asm volatile("cp.async.wait_group %0;\n" :: "n"(n) : "memory")

#define FMA2(d, a, b) asm("fma.rn.f32x2 %0, %1, %2, %0;" : "+l"(d) : "l"(a), "l"(b))

// ---------------------------------------------------------------------------
// Phase 1: Xg[t][b][h] = x[b][t][:] . Wg[h][:] + bias_g[h]   (3 gates)
// Block tile 128m x 64n, 256 threads, thread tile 8m x 4n, Kc = 16. (unchanged)
// ---------------------------------------------------------------------------
__global__ __launch_bounds__(256, 2) void gemm_in(
    const float* __restrict__ x,
    const float* __restrict__ W0, const float* __restrict__ W1, const float* __restrict__ W2,
    const float* __restrict__ c0, const float* __restrict__ c1, const float* __restrict__ c2)
{
    __shared__ float As[16][128];
    __shared__ float Bs[16][64];
    const int g = blockIdx.z;
    const float* W    = (g == 0) ? W0 : (g == 1) ? W1 : W2;
    const float* bias = (g == 0) ? c0 : (g == 1) ? c1 : c2;
    const int m0 = blockIdx.y * 128;
    const int n0 = blockIdx.x * 64;
    const int tid = threadIdx.x;
    const int n_thr = tid & 15;
    const int m_thr = tid >> 4;
    const int ar = tid >> 1, ak = (tid & 1) * 8;
    const int brow = tid >> 2, bk = (tid & 3) * 4;

    float acc[8][4];
#pragma unroll
    for (int i = 0; i < 8; i++)
#pragma unroll
        for (int j = 0; j < 4; j++) acc[i][j] = 0.f;

    for (int k0 = 0; k0 < II; k0 += 16) {
        float4 a0 = *(const float4*)&x[(size_t)(m0 + ar) * II + k0 + ak];
        float4 a1 = *(const float4*)&x[(size_t)(m0 + ar) * II + k0 + ak + 4];
        float4 bv = *(const float4*)&W[(size_t)(n0 + brow) * II + k0 + bk];
        As[ak + 0][ar] = a0.x; As[ak + 1][ar] = a0.y; As[ak + 2][ar] = a0.z; As[ak + 3][ar] = a0.w;
        As[ak + 4][ar] = a1.x; As[ak + 5][ar] = a1.y; As[ak + 6][ar] = a1.z; As[ak + 7][ar] = a1.w;
        Bs[bk + 0][brow] = bv.x; Bs[bk + 1][brow] = bv.y; Bs[bk + 2][brow] = bv.z; Bs[bk + 3][brow] = bv.w;
        __syncthreads();
#pragma unroll
        for (int k = 0; k < 16; k++) {
            float a[8], bb[4];
            *(float4*)&a[0] = *(const float4*)&As[k][m_thr * 8];
            *(float4*)&a[4] = *(const float4*)&As[k][m_thr * 8 + 4];
            *(float4*)&bb[0] = *(const float4*)&Bs[k][n_thr * 4];
#pragma unroll
            for (int i = 0; i < 8; i++)
#pragma unroll
                for (int j = 0; j < 4; j++) acc[i][j] += a[i] * bb[j];
        }
        __syncthreads();
    }

    float4 bs4 = *(const float4*)&bias[n0 + n_thr * 4];
#pragma unroll
    for (int i = 0; i < 8; i++) {
        int m = m0 + m_thr * 8 + i;
        int b = m >> 9;
        int t = m & 511;
        float4 o;
        o.x = acc[i][0] + bs4.x; o.y = acc[i][1] + bs4.y;
        o.z = acc[i][2] + bs4.z; o.w = acc[i][3] + bs4.w;
        *(float4*)&g_xg[(((size_t)g * TT + t) * BB + b) * HH + n0 + n_thr * 4] = o;
    }
}

// ---------------------------------------------------------------------------
// Phase 2 v2: persistent kernel, weights in REGISTERS (zero weight smem reads).
// 128 blocks x 256 threads (8 warps). Block owns 8 h-cols x 3 gates x 64 b.
// Warp w owns k-slice [w*128, w*128+128) for all 8 h-cols.
// Lane = h_in*4 + ksub: h-col h0+h_in, k-subrange ksub*4..+4 of each 16-float
// group; 96 weight floats/thread held as 48 packed b64 pairs for fma.rn.f32x2.
// h staged straight-copy via cp.async.cg (L1 bypass), 8-batch chunks, 2 bufs.
// Per (lane, b): 8 LDS.128 (64B/warp, broadcast x8, conflict-free) + 48 FFMA2.
// ksub 2-level shuffle reduce -> warp partials in smem -> block reduce+gates.
// ---------------------------------------------------------------------------
__global__ __launch_bounds__(NTHR, 1) void gru_steps(
    const float* __restrict__ Whr, const float* __restrict__ Whi, const float* __restrict__ Whn,
    float* __restrict__ out, int write_hlast)
{
    extern __shared__ float smem[];
    float* hbuf = smem;                    // [2][8][1024] = 16384 floats (64 KB)
    float* red  = smem + 2 * 8 * HH;       // [8w][64b][8h][3g] = 12288 floats (48 KB)

    const int tid  = threadIdx.x;
    const int warp = tid >> 5;             // 0..7 : k-slice
    const int lane = tid & 31;
    const int h_in = lane >> 2;            // 0..7 : h column within block
    const int ksub = lane & 3;             // 0..3 : 4-float subrange
    const int ht = blockIdx.x;
    const int h0 = ht * 8;
    const int kbase = warp * 128 + ksub * 4;

    // ---- Load weights into registers (persist across all 512 steps). ----
    // Pair p covers k = kbase + j*16 + p*2 .. +1.
    unsigned long long w2r[16], w2i[16], w2n[16];
    {
        const size_t row = (size_t)(h0 + h_in) * HH + kbase;
#pragma unroll
        for (int j = 0; j < 8; j++) {
#pragma unroll
            for (int p = 0; p < 2; p++) {
                w2r[j * 2 + p] = *(const unsigned long long*)&Whr[row + j * 16 + p * 2];
                w2i[j * 2 + p] = *(const unsigned long long*)&Whi[row + j * 16 + p * 2];
                w2n[j * 2 + p] = *(const unsigned long long*)&Whn[row + j * 16 + p * 2];
            }
        }
    }

    // Zero h[0] (this block's 512-float slice).
    {
        float* hz = &g_h[0][0];
        for (int i = tid; i < 512; i += NTHR) hz[ht * 512 + i] = 0.f;
    }

    unsigned gen = *(volatile unsigned*)&g_gen;
    gridbar(gen);

    for (int t = 0; t < TT; t++) {
        const float* hcur = g_h[t & 1];
        float* hnxt = g_h[(t & 1) ^ 1];

        // Stage chunk 0 (batches 0..7): straight 32KB copy, L1-bypassed.
        {
            const float* src = hcur;
            float* dst = hbuf;
#pragma unroll
            for (int i = 0; i < 8; i++) {
                int idx = (tid + i * NTHR) * 4;
                cp_async16(dst + idx, src + idx);
            }
            CP_COMMIT();
        }

        for (int c = 0; c < 8; c++) {
            if (c < 7) {
                __syncthreads();             // WAR: target buf fully consumed
                const float* src = hcur + (c + 1) * 8 * HH;
                float* dst = hbuf + ((c + 1) & 1) * (8 * HH);
#pragma unroll
                for (int i = 0; i < 8; i++) {
                    int idx = (tid + i * NTHR) * 4;
                    cp_async16(dst + idx, src + idx);
                }
                CP_COMMIT();
                CP_WAIT(1);                  // chunk c arrived
            } else {
                CP_WAIT(0);
            }
            __syncthreads();                 // chunk c visible to all warps

            const float* hc = hbuf + (c & 1) * (8 * HH) + kbase;
#pragma unroll
            for (int bb = 0; bb < 8; bb++) {
                const int b = c * 8 + bb;
                unsigned long long ar2 = 0, ai2 = 0, an2 = 0;
                const float* hrow = hc + bb * HH;
#pragma unroll
                for (int j = 0; j < 8; j++) {
                    union { float4 f; unsigned long long u[2]; } hv;
                    hv.f = *(const float4*)(hrow + j * 16);
                    FMA2(ar2, w2r[j * 2 + 0], hv.u[0]);
                    FMA2(ai2, w2i[j * 2 + 0], hv.u[0]);
                    FMA2(an2, w2n[j * 2 + 0], hv.u[0]);
                    FMA2(ar2, w2r[j * 2 + 1], hv.u[1]);
                    FMA2(ai2, w2i[j * 2 + 1], hv.u[1]);
                    FMA2(an2, w2n[j * 2 + 1], hv.u[1]);
                }
                union { unsigned long long u; float f[2]; } ur, ui, un;
                ur.u = ar2; ui.u = ai2; un.u = an2;
                float sr = ur.f[0] + ur.f[1];
                float si = ui.f[0] + ui.f[1];
                float sn = un.f[0] + un.f[1];
                // reduce over 4 ksub lanes (lanes h_in*4 .. +3)
                sr += __shfl_xor_sync(0xFFFFFFFFu, sr, 1);
                si += __shfl_xor_sync(0xFFFFFFFFu, si, 1);
                sn += __shfl_xor_sync(0xFFFFFFFFu, sn, 1);
                sr += __shfl_xor_sync(0xFFFFFFFFu, sr, 2);
                si += __shfl_xor_sync(0xFFFFFFFFu, si, 2);
                sn += __shfl_xor_sync(0xFFFFFFFFu, sn, 2);
                if (ksub == 0) {
                    float* rp = &red[(((warp * 64) + b) * 8 + h_in) * 3];
                    rp[0] = sr; rp[1] = si; rp[2] = sn;
                }
            }
        }

        __syncthreads();   // red[] complete

        // ---- Block reduce over 8 warp k-slices + gate epilogue. ----
        const size_t xoff = (size_t)t * BB * HH;
        const float* xr_p = g_xg + xoff;
        const float* xi_p = g_xg + (size_t)TT * BB * HH + xoff;
        const float* xn_p = g_xg + 2 * (size_t)TT * BB * HH + xoff;
#pragma unroll
        for (int o = tid; o < 512; o += NTHR) {
            const int b = o >> 3;
            const int hh = o & 7;
            float sr = 0.f, si = 0.f, sn = 0.f;
#pragma unroll
            for (int w = 0; w < 8; w++) {
                const float* rp = &red[(((w * 64) + b) * 8 + hh) * 3];
                sr += rp[0]; si += rp[1]; sn += rp[2];
            }
            const int h = h0 + hh;
            const size_t ix = (size_t)b * HH + h;
            float xr = xr_p[ix];
            float xi = xi_p[ix];
            float xn = xn_p[ix];
            float hp = __ldcg(&hcur[ix]);
            float rg = __fdividef(1.f, 1.f + __expf(-(xr + sr)));
            float ig = __fdividef(1.f, 1.f + __expf(-(xi + si)));
            float zi = xn + rg * sn;
            float ng = 1.f - __fdividef(2.f, __expf(2.f * zi) + 1.f);   // tanh(zi)
            float hn = (1.f - ig) * ng + ig * hp;
            hnxt[ix] = hn;
            out[((size_t)b * TT + t) * HH + h] = hn;
            if (write_hlast && t == TT - 1)
                out[(size_t)BB * TT * HH + ix] = hn;
        }

        if (t < TT - 1) gridbar(gen);
    }
}

extern "C" void kernel_launch(void* const* d_in, const int* in_sizes, int n_in,
                              void* d_out, int out_size) {
    const float* x   = (const float*)d_in[0];
    const float* Wir = (const float*)d_in[1];
    const float* Wii = (const float*)d_in[2];
    const float* Win = (const float*)d_in[3];
    const float* bir = (const float*)d_in[4];
    const float* bii = (const float*)d_in[5];
    const float* bin = (const float*)d_in[6];
    const float* Whr = (const float*)d_in[7];
    const float* Whi = (const float*)d_in[8];
    const float* Whn = (const float*)d_in[9];
    float* out = (float*)d_out;

    // Phase 1: input-side projections for all 3 gates.
    dim3 g1(HH / 64, (BB * TT) / 128, 3);
    gemm_in<<<g1, 256>>>(x, Wir, Wii, Win, bir, bii, bin);

    // Phase 2: persistent recurrence kernel.
    const int smem_bytes = (2 * 8 * HH + 8 * 64 * 8 * 3) * (int)sizeof(float);  // 114688
    cudaFuncSetAttribute(gru_steps, cudaFuncAttributeMaxDynamicSharedMemorySize, smem_bytes);
    int write_hlast = (out_size >= BB * TT * HH + BB * HH) ? 1 : 0;
    gru_steps<<<NBLK, NTHR, smem_bytes>>>(Whr, Whi, Whn, out, write_hlast);
}